// round 5
// baseline (speedup 1.0000x reference)
#include <cuda_runtime.h>
#include <math.h>

#define BATCH 8
#define NPTS 2048
#define COLSPLIT 2
#define COLS (NPTS / COLSPLIT)      // 1024 columns per block
#define ROWBLOCKS 64                // row-blocks per batch
#define ROWS_PER_BLOCK 32           // 8 warps * 4 rows
#define PARTS (COLSPLIT * ROWBLOCKS)  // 128 partials per batch

// Per-block partials [T(9), v(3)] and completion counters.
__device__ float g_part[BATCH][PARTS][12];
__device__ unsigned int g_count[BATCH];   // zero-init; reset each call

// ---------------------------------------------------------------------------
// Fused kernel. grid = (PARTS, BATCH), block = 256 (8 warps).
// blockIdx.x & 1 selects the column half; blockIdx.x >> 1 the 32-row band.
// Each warp streams 4 rows x 1024 cols (4 independent LDG.128 / iter).
// Last block per batch reduces partials -> means, S, polar, R, t.
// ---------------------------------------------------------------------------
__global__ void __launch_bounds__(256, 6) fused_kernel(
    const float* __restrict__ P,
    const float* __restrict__ Q,
    const float* __restrict__ M,
    float* __restrict__ out) {
    const int b = blockIdx.y;
    const int tid = threadIdx.x;
    const int warp = tid >> 5;
    const int lane = tid & 31;
    const int colh = blockIdx.x & (COLSPLIT - 1);
    const int rowblk = blockIdx.x >> 1;

    __shared__ float p0[COLS], p1[COLS], p2[COLS];
    __shared__ float sacc[8][12];
    __shared__ float warpSums[8][6];
    __shared__ float sTv[12];
    __shared__ int sIsLast;

    const float* Pb = P + (size_t)b * NPTS * 3;
    const float* Qb = Q + (size_t)b * NPTS * 3;

    // stage this block's column-half of P into smem (SoA)
    {
        const float* Pcol = Pb + colh * COLS * 3;
        for (int i = tid; i < COLS * 3; i += 256) {
            float v = Pcol[i];
            int pt = i / 3, c = i - pt * 3;
            float* dst = (c == 0) ? p0 : (c == 1) ? p1 : p2;
            dst[pt] = v;
        }
    }
    __syncthreads();

    // ---------------- Phase 1: stream 4 rows x COLS of M per warp ----------------
    const float* Mb = M + (size_t)b * NPTS * NPTS;
    const int n0 = rowblk * ROWS_PER_BLOCK + warp * 4;
    const float4* Rbase =
        reinterpret_cast<const float4*>(Mb + (size_t)n0 * NPTS + colh * COLS);

    float d0x = 0.f, d0y = 0.f, d0z = 0.f;
    float d1x = 0.f, d1y = 0.f, d1z = 0.f;
    float d2x = 0.f, d2y = 0.f, d2z = 0.f;
    float d3x = 0.f, d3y = 0.f, d3z = 0.f;

    #pragma unroll 4
    for (int it = 0; it < COLS / 128; it++) {     // 8 iterations
        int m4 = it * 32 + lane;
        float4 mv0 = __ldcs(&Rbase[m4]);                        // row n0
        float4 mv1 = __ldcs(&Rbase[m4 + 1 * (NPTS / 4)]);       // row n0+1
        float4 mv2 = __ldcs(&Rbase[m4 + 2 * (NPTS / 4)]);       // row n0+2
        float4 mv3 = __ldcs(&Rbase[m4 + 3 * (NPTS / 4)]);       // row n0+3
        int m = m4 * 4;
        float4 a  = *reinterpret_cast<const float4*>(&p0[m]);
        float4 bb = *reinterpret_cast<const float4*>(&p1[m]);
        float4 c  = *reinterpret_cast<const float4*>(&p2[m]);
        d0x += mv0.x * a.x  + mv0.y * a.y  + mv0.z * a.z  + mv0.w * a.w;
        d0y += mv0.x * bb.x + mv0.y * bb.y + mv0.z * bb.z + mv0.w * bb.w;
        d0z += mv0.x * c.x  + mv0.y * c.y  + mv0.z * c.z  + mv0.w * c.w;
        d1x += mv1.x * a.x  + mv1.y * a.y  + mv1.z * a.z  + mv1.w * a.w;
        d1y += mv1.x * bb.x + mv1.y * bb.y + mv1.z * bb.z + mv1.w * bb.w;
        d1z += mv1.x * c.x  + mv1.y * c.y  + mv1.z * c.z  + mv1.w * c.w;
        d2x += mv2.x * a.x  + mv2.y * a.y  + mv2.z * a.z  + mv2.w * a.w;
        d2y += mv2.x * bb.x + mv2.y * bb.y + mv2.z * bb.z + mv2.w * bb.w;
        d2z += mv2.x * c.x  + mv2.y * c.y  + mv2.z * c.z  + mv2.w * c.w;
        d3x += mv3.x * a.x  + mv3.y * a.y  + mv3.z * a.z  + mv3.w * a.w;
        d3y += mv3.x * bb.x + mv3.y * bb.y + mv3.z * bb.z + mv3.w * bb.w;
        d3z += mv3.x * c.x  + mv3.y * c.y  + mv3.z * c.z  + mv3.w * c.w;
    }

    #pragma unroll
    for (int off = 16; off > 0; off >>= 1) {
        d0x += __shfl_xor_sync(0xffffffffu, d0x, off);
        d0y += __shfl_xor_sync(0xffffffffu, d0y, off);
        d0z += __shfl_xor_sync(0xffffffffu, d0z, off);
        d1x += __shfl_xor_sync(0xffffffffu, d1x, off);
        d1y += __shfl_xor_sync(0xffffffffu, d1y, off);
        d1z += __shfl_xor_sync(0xffffffffu, d1z, off);
        d2x += __shfl_xor_sync(0xffffffffu, d2x, off);
        d2y += __shfl_xor_sync(0xffffffffu, d2y, off);
        d2z += __shfl_xor_sync(0xffffffffu, d2z, off);
        d3x += __shfl_xor_sync(0xffffffffu, d3x, off);
        d3y += __shfl_xor_sync(0xffffffffu, d3y, off);
        d3z += __shfl_xor_sync(0xffffffffu, d3z, off);
    }

    if (lane == 0) {
        const float* q = Qb + n0 * 3;
        float q0x = q[0], q0y = q[1],  q0z = q[2];
        float q1x = q[3], q1y = q[4],  q1z = q[5];
        float q2x = q[6], q2y = q[7],  q2z = q[8];
        float q3x = q[9], q3y = q[10], q3z = q[11];
        sacc[warp][0] = d0x * q0x + d1x * q1x + d2x * q2x + d3x * q3x;
        sacc[warp][1] = d0x * q0y + d1x * q1y + d2x * q2y + d3x * q3y;
        sacc[warp][2] = d0x * q0z + d1x * q1z + d2x * q2z + d3x * q3z;
        sacc[warp][3] = d0y * q0x + d1y * q1x + d2y * q2x + d3y * q3x;
        sacc[warp][4] = d0y * q0y + d1y * q1y + d2y * q2y + d3y * q3y;
        sacc[warp][5] = d0y * q0z + d1y * q1z + d2y * q2z + d3y * q3z;
        sacc[warp][6] = d0z * q0x + d1z * q1x + d2z * q2x + d3z * q3x;
        sacc[warp][7] = d0z * q0y + d1z * q1y + d2z * q2y + d3z * q3y;
        sacc[warp][8] = d0z * q0z + d1z * q1z + d2z * q2z + d3z * q3z;
        sacc[warp][9]  = d0x + d1x + d2x + d3x;
        sacc[warp][10] = d0y + d1y + d2y + d3y;
        sacc[warp][11] = d0z + d1z + d2z + d3z;
    }
    __syncthreads();
    if (tid < 12) {
        float s = 0.f;
        #pragma unroll
        for (int w = 0; w < 8; w++) s += sacc[w][tid];
        g_part[b][blockIdx.x][tid] = s;
    }
    __threadfence();
    __syncthreads();

    // ---------------- Phase 2: last block of this batch finishes ----------------
    if (tid == 0) {
        unsigned int old = atomicAdd(&g_count[b], 1u);
        sIsLast = (old == PARTS - 1u) ? 1 : 0;
    }
    __syncthreads();
    if (!sIsLast) return;
    __threadfence();   // acquire: make other blocks' g_part writes visible

    // --- means of P and Q via float4 triples from global ---
    float sp0 = 0.f, sp1 = 0.f, sp2 = 0.f;
    float sq0 = 0.f, sq1 = 0.f, sq2 = 0.f;
    const float4* P4 = reinterpret_cast<const float4*>(Pb);
    const float4* Q4 = reinterpret_cast<const float4*>(Qb);
    #pragma unroll
    for (int t = 0; t < 2; t++) {
        int tr = tid + t * 256;               // triple index, 512 total
        float4 A = P4[tr * 3 + 0];
        float4 Bv = P4[tr * 3 + 1];
        float4 C = P4[tr * 3 + 2];
        sp0 += A.x + A.w + Bv.z + C.y;
        sp1 += A.y + Bv.x + Bv.w + C.z;
        sp2 += A.z + Bv.y + C.x + C.w;
        float4 A2 = Q4[tr * 3 + 0];
        float4 B2 = Q4[tr * 3 + 1];
        float4 C2 = Q4[tr * 3 + 2];
        sq0 += A2.x + A2.w + B2.z + C2.y;
        sq1 += A2.y + B2.x + B2.w + C2.z;
        sq2 += A2.z + B2.y + C2.x + C2.w;
    }
    #pragma unroll
    for (int off = 16; off > 0; off >>= 1) {
        sp0 += __shfl_xor_sync(0xffffffffu, sp0, off);
        sp1 += __shfl_xor_sync(0xffffffffu, sp1, off);
        sp2 += __shfl_xor_sync(0xffffffffu, sp2, off);
        sq0 += __shfl_xor_sync(0xffffffffu, sq0, off);
        sq1 += __shfl_xor_sync(0xffffffffu, sq1, off);
        sq2 += __shfl_xor_sync(0xffffffffu, sq2, off);
    }
    if (lane == 0) {
        warpSums[warp][0] = sp0; warpSums[warp][1] = sp1; warpSums[warp][2] = sp2;
        warpSums[warp][3] = sq0; warpSums[warp][4] = sq1; warpSums[warp][5] = sq2;
    }

    // --- warp 0 reduces the PARTS x 12 partials ---
    if (warp == 0) {
        float Tv[12];
        #pragma unroll
        for (int j = 0; j < 12; j++) Tv[j] = 0.f;
        #pragma unroll
        for (int r = 0; r < PARTS / 32; r++) {
            const float* row = g_part[b][lane + r * 32];
            #pragma unroll
            for (int j = 0; j < 12; j++) Tv[j] += row[j];
        }
        #pragma unroll
        for (int off = 16; off > 0; off >>= 1) {
            #pragma unroll
            for (int j = 0; j < 12; j++)
                Tv[j] += __shfl_xor_sync(0xffffffffu, Tv[j], off);
        }
        if (lane == 0) {
            #pragma unroll
            for (int j = 0; j < 12; j++) sTv[j] = Tv[j];
        }
    }
    __syncthreads();

    if (tid == 0) {
        g_count[b] = 0u;   // reset for next graph replay

        float mS[6];
        #pragma unroll
        for (int j = 0; j < 6; j++) {
            float s = 0.f;
            #pragma unroll
            for (int w = 0; w < 8; w++) s += warpSums[w][j];
            mS[j] = s;
        }
        const float inv = 1.0f / (float)NPTS;
        float mp0 = mS[0] * inv, mp1 = mS[1] * inv, mp2 = mS[2] * inv;
        float mq0 = mS[3] * inv, mq1 = mS[4] * inv, mq2 = mS[5] * inv;

        float v0 = sTv[9], v1 = sTv[10], v2 = sTv[11];
        float X[9];
        X[0] = sTv[0] - v0 * mq0; X[1] = sTv[1] - v0 * mq1; X[2] = sTv[2] - v0 * mq2;
        X[3] = sTv[3] - v1 * mq0; X[4] = sTv[4] - v1 * mq1; X[5] = sTv[5] - v1 * mq2;
        X[6] = sTv[6] - v2 * mq0; X[7] = sTv[7] - v2 * mq1; X[8] = sTv[8] - v2 * mq2;

        // Newton polar iteration (det-scaled): X -> 0.5*(g*X + sgn*g^2*cof(X))
        #pragma unroll
        for (int it = 0; it < 12; it++) {
            float C[9];
            C[0] = X[4] * X[8] - X[5] * X[7];
            C[1] = X[5] * X[6] - X[3] * X[8];
            C[2] = X[3] * X[7] - X[4] * X[6];
            C[3] = X[2] * X[7] - X[1] * X[8];
            C[4] = X[0] * X[8] - X[2] * X[6];
            C[5] = X[1] * X[6] - X[0] * X[7];
            C[6] = X[1] * X[5] - X[2] * X[4];
            C[7] = X[2] * X[3] - X[0] * X[5];
            C[8] = X[0] * X[4] - X[1] * X[3];
            float det = X[0] * C[0] + X[1] * C[1] + X[2] * C[2];
            float g = rcbrtf(fabsf(det));
            float g2s = copysignf(g * g, det);
            #pragma unroll
            for (int i = 0; i < 9; i++) X[i] = 0.5f * (g * X[i] + g2s * C[i]);
        }

        float R[9];
        #pragma unroll
        for (int i = 0; i < 3; i++)
            #pragma unroll
            for (int j = 0; j < 3; j++)
                R[i * 3 + j] = X[j * 3 + i];

        float* Rout = out + b * 9;
        float* tout = out + BATCH * 9 + b * 3;
        float mp[3] = {mp0, mp1, mp2};
        float mq[3] = {mq0, mq1, mq2};
        #pragma unroll
        for (int i = 0; i < 3; i++) {
            float ti = mq[i];
            #pragma unroll
            for (int j = 0; j < 3; j++) {
                Rout[i * 3 + j] = R[i * 3 + j];
                ti -= R[i * 3 + j] * mp[j];
            }
            tout[i] = ti;
        }
    }
}

// ---------------------------------------------------------------------------
extern "C" void kernel_launch(void* const* d_in, const int* in_sizes, int n_in,
                              void* d_out, int out_size) {
    const float* P = (const float*)d_in[0];   // Ppc [8,2048,3]
    const float* Q = (const float*)d_in[1];   // Qpc [8,2048,3]
    const float* M = (const float*)d_in[2];   // M   [8,2048,2048]
    float* out = (float*)d_out;               // 72 R + 24 t

    fused_kernel<<<dim3(PARTS, BATCH), 256>>>(P, Q, M, out);
}

// round 7
// speedup vs baseline: 1.3308x; 1.3308x over previous
#include <cuda_runtime.h>
#include <math.h>
#include <stdint.h>

#define BATCH 8
#define NPTS 2048
#define ROWS_PB 32                 // rows of M per block (8 warps * 4 rows)
#define CHUNK 64                   // columns per pipeline stage
#define NIT (NPTS / CHUNK)         // 32 pipeline iterations
#define STAGES 4                   // smem ring depth (3 in flight)
#define GRIDX (NPTS / ROWS_PB)     // 64 blocks per batch

__device__ float g_part[BATCH][GRIDX][12];
__device__ unsigned int g_count[BATCH];   // zero-init; reset each call

__device__ __forceinline__ void cp_async16(uint32_t dst, const float* src) {
    asm volatile("cp.async.cg.shared.global [%0], [%1], 16;\n"
                 :: "r"(dst), "l"(src));
}
__device__ __forceinline__ void cp_commit() {
    asm volatile("cp.async.commit_group;\n" ::: "memory");
}
template <int N>
__device__ __forceinline__ void cp_wait() {
    asm volatile("cp.async.wait_group %0;\n" :: "n"(N) : "memory");
}

// ---------------------------------------------------------------------------
// Fused kernel. grid = (GRIDX, BATCH), block = 256 (8 warps).
// cp.async stages M tiles (32 rows x 64 cols) through a 4-deep smem ring.
// Each warp owns 4 rows; lane l owns cols {2l, 2l+1} of each 64-col chunk.
// Last block per batch reduces partials -> means, S, polar, R, t.
// ---------------------------------------------------------------------------
__global__ void __launch_bounds__(256) fused_kernel(
    const float* __restrict__ P,
    const float* __restrict__ Q,
    const float* __restrict__ M,
    float* __restrict__ out) {
    const int b = blockIdx.y;
    const int rowblk = blockIdx.x;
    const int tid = threadIdx.x;
    const int warp = tid >> 5;
    const int lane = tid & 31;

    __shared__ float stage[STAGES * ROWS_PB * CHUNK];   // 32 KB
    __shared__ float sacc[8][12];
    __shared__ float warpSums[8][6];
    __shared__ float sTv[12];
    __shared__ int sIsLast;

    const float* Pb = P + (size_t)b * NPTS * 3;
    const float* Qb = Q + (size_t)b * NPTS * 3;
    const float* Mb = M + (size_t)b * NPTS * NPTS + (size_t)rowblk * ROWS_PB * NPTS;

    const uint32_t sbase = (uint32_t)__cvta_generic_to_shared(stage);

    // cp.async issue for pipeline stage `it`: 8KB tile, 2 x 16B per thread.
    const int ir = tid >> 4;               // 0..15
    const int ic = (tid & 15) * 4;         // column group (floats)
    const float* g0 = Mb + (size_t)ir * NPTS + ic;
    const float* g1 = Mb + (size_t)(ir + 16) * NPTS + ic;
    const uint32_t s0 = sbase + (uint32_t)((ir * CHUNK + ic) * 4);
    const uint32_t s1 = sbase + (uint32_t)(((ir + 16) * CHUNK + ic) * 4);

    auto issue = [&](int it) {
        uint32_t so = (uint32_t)((it & (STAGES - 1)) * ROWS_PB * CHUNK * 4);
        cp_async16(s0 + so, g0 + (size_t)it * CHUNK);
        cp_async16(s1 + so, g1 + (size_t)it * CHUNK);
    };

    // prologue: stages 0..STAGES-2
    #pragma unroll
    for (int s = 0; s < STAGES - 1; s++) {
        issue(s);
        cp_commit();
    }

    float d0x = 0.f, d0y = 0.f, d0z = 0.f;
    float d1x = 0.f, d1y = 0.f, d1z = 0.f;
    float d2x = 0.f, d2y = 0.f, d2z = 0.f;
    float d3x = 0.f, d3y = 0.f, d3z = 0.f;

    const int c = 2 * lane;                       // lane's first column in chunk
    const float* warpStageBase = stage + warp * 4 * CHUNK + c;

    for (int it = 0; it < NIT; it++) {
        if (it + STAGES - 1 < NIT) issue(it + STAGES - 1);
        cp_commit();
        cp_wait<STAGES - 1>();
        __syncthreads();

        // P values for global cols (it*CHUNK + c), (it*CHUNK + c + 1):
        // 6 consecutive floats at Pb + col*3 (8B aligned since c even)
        const float2* pp = reinterpret_cast<const float2*>(Pb + (size_t)(it * CHUNK + c) * 3);
        float2 pA = __ldg(pp + 0);    // px0 py0
        float2 pB = __ldg(pp + 1);    // pz0 px1
        float2 pC = __ldg(pp + 2);    // py1 pz1

        const float* st = warpStageBase + ((it & (STAGES - 1)) * ROWS_PB * CHUNK);
        float2 m0 = *reinterpret_cast<const float2*>(st + 0 * CHUNK);
        float2 m1 = *reinterpret_cast<const float2*>(st + 1 * CHUNK);
        float2 m2 = *reinterpret_cast<const float2*>(st + 2 * CHUNK);
        float2 m3 = *reinterpret_cast<const float2*>(st + 3 * CHUNK);

        d0x += m0.x * pA.x + m0.y * pB.y;
        d0y += m0.x * pA.y + m0.y * pC.x;
        d0z += m0.x * pB.x + m0.y * pC.y;
        d1x += m1.x * pA.x + m1.y * pB.y;
        d1y += m1.x * pA.y + m1.y * pC.x;
        d1z += m1.x * pB.x + m1.y * pC.y;
        d2x += m2.x * pA.x + m2.y * pB.y;
        d2y += m2.x * pA.y + m2.y * pC.x;
        d2z += m2.x * pB.x + m2.y * pC.y;
        d3x += m3.x * pA.x + m3.y * pB.y;
        d3y += m3.x * pA.y + m3.y * pC.x;
        d3z += m3.x * pB.x + m3.y * pC.y;

        __syncthreads();
    }

    // warp butterfly reduce the 12 dot partials
    #pragma unroll
    for (int off = 16; off > 0; off >>= 1) {
        d0x += __shfl_xor_sync(0xffffffffu, d0x, off);
        d0y += __shfl_xor_sync(0xffffffffu, d0y, off);
        d0z += __shfl_xor_sync(0xffffffffu, d0z, off);
        d1x += __shfl_xor_sync(0xffffffffu, d1x, off);
        d1y += __shfl_xor_sync(0xffffffffu, d1y, off);
        d1z += __shfl_xor_sync(0xffffffffu, d1z, off);
        d2x += __shfl_xor_sync(0xffffffffu, d2x, off);
        d2y += __shfl_xor_sync(0xffffffffu, d2y, off);
        d2z += __shfl_xor_sync(0xffffffffu, d2z, off);
        d3x += __shfl_xor_sync(0xffffffffu, d3x, off);
        d3y += __shfl_xor_sync(0xffffffffu, d3y, off);
        d3z += __shfl_xor_sync(0xffffffffu, d3z, off);
    }

    const int n0 = rowblk * ROWS_PB + warp * 4;
    if (lane == 0) {
        const float* q = Qb + n0 * 3;
        float q0x = q[0], q0y = q[1],  q0z = q[2];
        float q1x = q[3], q1y = q[4],  q1z = q[5];
        float q2x = q[6], q2y = q[7],  q2z = q[8];
        float q3x = q[9], q3y = q[10], q3z = q[11];
        sacc[warp][0] = d0x * q0x + d1x * q1x + d2x * q2x + d3x * q3x;
        sacc[warp][1] = d0x * q0y + d1x * q1y + d2x * q2y + d3x * q3y;
        sacc[warp][2] = d0x * q0z + d1x * q1z + d2x * q2z + d3x * q3z;
        sacc[warp][3] = d0y * q0x + d1y * q1x + d2y * q2x + d3y * q3x;
        sacc[warp][4] = d0y * q0y + d1y * q1y + d2y * q2y + d3y * q3y;
        sacc[warp][5] = d0y * q0z + d1y * q1z + d2y * q2z + d3y * q3z;
        sacc[warp][6] = d0z * q0x + d1z * q1x + d2z * q2x + d3z * q3x;
        sacc[warp][7] = d0z * q0y + d1z * q1y + d2z * q2y + d3z * q3y;
        sacc[warp][8] = d0z * q0z + d1z * q1z + d2z * q2z + d3z * q3z;
        sacc[warp][9]  = d0x + d1x + d2x + d3x;
        sacc[warp][10] = d0y + d1y + d2y + d3y;
        sacc[warp][11] = d0z + d1z + d2z + d3z;
    }
    __syncthreads();
    if (tid < 12) {
        float s = 0.f;
        #pragma unroll
        for (int w = 0; w < 8; w++) s += sacc[w][tid];
        g_part[b][rowblk][tid] = s;
    }
    __threadfence();
    __syncthreads();

    // ---------------- last block of this batch finishes ----------------
    if (tid == 0) {
        unsigned int old = atomicAdd(&g_count[b], 1u);
        sIsLast = (old == GRIDX - 1u) ? 1 : 0;
    }
    __syncthreads();
    if (!sIsLast) return;
    __threadfence();   // acquire: other blocks' g_part writes visible

    // --- means of P and Q via float4 triples from global ---
    float sp0 = 0.f, sp1 = 0.f, sp2 = 0.f;
    float sq0 = 0.f, sq1 = 0.f, sq2 = 0.f;
    const float4* P4 = reinterpret_cast<const float4*>(Pb);
    const float4* Q4 = reinterpret_cast<const float4*>(Qb);
    #pragma unroll
    for (int t = 0; t < 2; t++) {
        int tr = tid + t * 256;               // triple index, 512 total
        float4 A = P4[tr * 3 + 0];
        float4 Bv = P4[tr * 3 + 1];
        float4 C = P4[tr * 3 + 2];
        sp0 += A.x + A.w + Bv.z + C.y;
        sp1 += A.y + Bv.x + Bv.w + C.z;
        sp2 += A.z + Bv.y + C.x + C.w;
        float4 A2 = Q4[tr * 3 + 0];
        float4 B2 = Q4[tr * 3 + 1];
        float4 C2 = Q4[tr * 3 + 2];
        sq0 += A2.x + A2.w + B2.z + C2.y;
        sq1 += A2.y + B2.x + B2.w + C2.z;
        sq2 += A2.z + B2.y + C2.x + C2.w;
    }
    #pragma unroll
    for (int off = 16; off > 0; off >>= 1) {
        sp0 += __shfl_xor_sync(0xffffffffu, sp0, off);
        sp1 += __shfl_xor_sync(0xffffffffu, sp1, off);
        sp2 += __shfl_xor_sync(0xffffffffu, sp2, off);
        sq0 += __shfl_xor_sync(0xffffffffu, sq0, off);
        sq1 += __shfl_xor_sync(0xffffffffu, sq1, off);
        sq2 += __shfl_xor_sync(0xffffffffu, sq2, off);
    }
    if (lane == 0) {
        warpSums[warp][0] = sp0; warpSums[warp][1] = sp1; warpSums[warp][2] = sp2;
        warpSums[warp][3] = sq0; warpSums[warp][4] = sq1; warpSums[warp][5] = sq2;
    }

    // --- warp 0 reduces the GRIDX x 12 partials ---
    if (warp == 0) {
        float Tv[12];
        #pragma unroll
        for (int j = 0; j < 12; j++) Tv[j] = 0.f;
        #pragma unroll
        for (int r = 0; r < GRIDX / 32; r++) {
            const float* row = g_part[b][lane + r * 32];
            #pragma unroll
            for (int j = 0; j < 12; j++) Tv[j] += row[j];
        }
        #pragma unroll
        for (int off = 16; off > 0; off >>= 1) {
            #pragma unroll
            for (int j = 0; j < 12; j++)
                Tv[j] += __shfl_xor_sync(0xffffffffu, Tv[j], off);
        }
        if (lane == 0) {
            #pragma unroll
            for (int j = 0; j < 12; j++) sTv[j] = Tv[j];
        }
    }
    __syncthreads();

    if (tid == 0) {
        g_count[b] = 0u;   // reset for next graph replay

        float mS[6];
        #pragma unroll
        for (int j = 0; j < 6; j++) {
            float s = 0.f;
            #pragma unroll
            for (int w = 0; w < 8; w++) s += warpSums[w][j];
            mS[j] = s;
        }
        const float inv = 1.0f / (float)NPTS;
        float mp0 = mS[0] * inv, mp1 = mS[1] * inv, mp2 = mS[2] * inv;
        float mq0 = mS[3] * inv, mq1 = mS[4] * inv, mq2 = mS[5] * inv;

        float v0 = sTv[9], v1 = sTv[10], v2 = sTv[11];
        float X[9];
        X[0] = sTv[0] - v0 * mq0; X[1] = sTv[1] - v0 * mq1; X[2] = sTv[2] - v0 * mq2;
        X[3] = sTv[3] - v1 * mq0; X[4] = sTv[4] - v1 * mq1; X[5] = sTv[5] - v1 * mq2;
        X[6] = sTv[6] - v2 * mq0; X[7] = sTv[7] - v2 * mq1; X[8] = sTv[8] - v2 * mq2;

        // Newton polar iteration (det-scaled): X -> 0.5*(g*X + sgn*g^2*cof(X))
        #pragma unroll
        for (int itn = 0; itn < 12; itn++) {
            float C[9];
            C[0] = X[4] * X[8] - X[5] * X[7];
            C[1] = X[5] * X[6] - X[3] * X[8];
            C[2] = X[3] * X[7] - X[4] * X[6];
            C[3] = X[2] * X[7] - X[1] * X[8];
            C[4] = X[0] * X[8] - X[2] * X[6];
            C[5] = X[1] * X[6] - X[0] * X[7];
            C[6] = X[1] * X[5] - X[2] * X[4];
            C[7] = X[2] * X[3] - X[0] * X[5];
            C[8] = X[0] * X[4] - X[1] * X[3];
            float det = X[0] * C[0] + X[1] * C[1] + X[2] * C[2];
            float g = rcbrtf(fabsf(det));
            float g2s = copysignf(g * g, det);
            #pragma unroll
            for (int i = 0; i < 9; i++) X[i] = 0.5f * (g * X[i] + g2s * C[i]);
        }

        float R[9];
        #pragma unroll
        for (int i = 0; i < 3; i++)
            #pragma unroll
            for (int j = 0; j < 3; j++)
                R[i * 3 + j] = X[j * 3 + i];

        float* Rout = out + b * 9;
        float* tout = out + BATCH * 9 + b * 3;
        float mp[3] = {mp0, mp1, mp2};
        float mq[3] = {mq0, mq1, mq2};
        #pragma unroll
        for (int i = 0; i < 3; i++) {
            float ti = mq[i];
            #pragma unroll
            for (int j = 0; j < 3; j++) {
                Rout[i * 3 + j] = R[i * 3 + j];
                ti -= R[i * 3 + j] * mp[j];
            }
            tout[i] = ti;
        }
    }
}

// ---------------------------------------------------------------------------
extern "C" void kernel_launch(void* const* d_in, const int* in_sizes, int n_in,
                              void* d_out, int out_size) {
    const float* P = (const float*)d_in[0];   // Ppc [8,2048,3]
    const float* Q = (const float*)d_in[1];   // Qpc [8,2048,3]
    const float* M = (const float*)d_in[2];   // M   [8,2048,2048]
    float* out = (float*)d_out;               // 72 R + 24 t

    fused_kernel<<<dim3(GRIDX, BATCH), 256>>>(P, Q, M, out);
}